// round 15
// baseline (speedup 1.0000x reference)
#include <cuda_runtime.h>
#include <cuda_fp16.h>
#include <cstdint>
#include <math.h>

// ───────────────────────── problem constants ─────────────────────────
constexpr int Bsz = 4, S = 2048, E = 1024, D = 1024;

// Tiled-swizzled image format for all fp16 operands:
//   tile (rb, kb) = 128 rows × 64 k = 16KB contiguous at (rb*NKB + kb)*16384,
//   element (ir, ik) at byte ir*128 + ((ik*2) ^ ((ir&7)<<4)).
__device__ __half g_x[(size_t)Bsz * S * E];      // rows=token, k=e   (NKB 16)
__device__ __half g_W[(size_t)3 * E * D];        // per z: rows=n, k=e (NKB 16)
__device__ __half g_q[(size_t)Bsz * S * D];      // rows=token, k=d   (NKB 16)
__device__ __half g_k[(size_t)Bsz * S * D];      // rows=token, k=d   (NKB 16)
__device__ __half g_v[(size_t)Bsz * D * S];      // per b: rows=d, k=s (NKB 32)
__device__ __half g_p[(size_t)Bsz * S * S];      // exp'd unnormalized probs (NKB 32)
__device__ float  g_rs[(size_t)Bsz * S * 32];    // per-row partial sums (32 slots)

__device__ __forceinline__ __half* img_addr(__half* base, int r, int k, int nkb) {
    size_t tile = (size_t)((r >> 7) * nkb + (k >> 6));
    uint32_t off = (uint32_t)((r & 127) * 128) +
                   ((((uint32_t)(k & 63)) * 2) ^ (((uint32_t)r & 7) << 4));
    return (__half*)((char*)base + (tile << 14) + off);
}

// ───────────────────────── tile config ───────────────────────────────
constexpr int NTH = 256;
constexpr int TILE_B = 16384;                  // 128 x 64 halfs
constexpr int STAGE_B = 2 * TILE_B;            // A, B
constexpr int SMEM_MBAR = 3 * STAGE_B;         // 98304
constexpr int SMEM_TOTAL = SMEM_MBAR + 64;

// ───────────────────────── PTX helpers ───────────────────────────────
__device__ __forceinline__ uint32_t s2u(const void* p) {
    uint32_t a;
    asm("{ .reg .u64 t; cvta.to.shared.u64 t, %1; cvt.u32.u64 %0, t; }" : "=r"(a) : "l"(p));
    return a;
}
__device__ __forceinline__ void mbar_init(uint32_t addr, uint32_t cnt) {
    asm volatile("mbarrier.init.shared.b64 [%0], %1;" :: "r"(addr), "r"(cnt) : "memory");
}
__device__ __forceinline__ void mbar_expect_tx(uint32_t addr, uint32_t bytes) {
    asm volatile("mbarrier.arrive.expect_tx.shared::cta.b64 _, [%0], %1;"
                 :: "r"(addr), "r"(bytes) : "memory");
}
__device__ __forceinline__ void mbar_arrive(uint32_t addr) {
    asm volatile("mbarrier.arrive.shared.b64 _, [%0];" :: "r"(addr) : "memory");
}
__device__ __forceinline__ void mbar_wait(uint32_t addr, uint32_t parity) {
    asm volatile(
        "{\n\t.reg .pred P;\n\t"
        "WL_%=:\n\t"
        "mbarrier.try_wait.parity.acquire.cta.shared::cta.b64 P, [%0], %1, 0x989680;\n\t"
        "@!P bra WL_%=;\n\t}"
        :: "r"(addr), "r"(parity) : "memory");
}
__device__ __forceinline__ void bulk_g2s(uint32_t sdst, const void* gsrc, uint32_t bytes,
                                         uint32_t mbar) {
    asm volatile(
        "cp.async.bulk.shared::cluster.global.mbarrier::complete_tx::bytes "
        "[%0], [%1], %2, [%3];"
        :: "r"(sdst), "l"(gsrc), "r"(bytes), "r"(mbar) : "memory");
}
__device__ __forceinline__ void ldmatrix4(uint32_t* r, uint32_t addr) {
    asm volatile("ldmatrix.sync.aligned.m8n8.x4.shared.b16 {%0,%1,%2,%3}, [%4];"
                 : "=r"(r[0]), "=r"(r[1]), "=r"(r[2]), "=r"(r[3]) : "r"(addr));
}
__device__ __forceinline__ void mma16816f(float* c, const uint32_t* a, const uint32_t* b) {
    asm volatile(
        "mma.sync.aligned.m16n8k16.row.col.f32.f16.f16.f32 "
        "{%0,%1,%2,%3}, {%4,%5,%6,%7}, {%8,%9}, {%0,%1,%2,%3};"
        : "+f"(c[0]), "+f"(c[1]), "+f"(c[2]), "+f"(c[3])
        : "r"(a[0]), "r"(a[1]), "r"(a[2]), "r"(a[3]), "r"(b[0]), "r"(b[1]));
}
__device__ __forceinline__ void mma16816h(uint32_t* c, const uint32_t* a, const uint32_t* b) {
    asm volatile(
        "mma.sync.aligned.m16n8k16.row.col.f16.f16.f16.f16 "
        "{%0,%1}, {%2,%3,%4,%5}, {%6,%7}, {%0,%1};"
        : "+r"(c[0]), "+r"(c[1])
        : "r"(a[0]), "r"(a[1]), "r"(a[2]), "r"(a[3]), "r"(b[0]), "r"(b[1]));
}

// ───────────────────────── pipeline machinery (shared) ───────────────
struct PipeCtx {
    uint32_t sbase, mb0;
    const char *Aimg, *Bimg;
    int by, bx, NC;
};

__device__ __forceinline__ void pipe_init(PipeCtx& P, int tid) {
    if (tid == 0) {
        mbar_init(P.mb0, 1);      mbar_init(P.mb0 + 8, 1);  mbar_init(P.mb0 + 16, 1);
        mbar_init(P.mb0 + 24, 8); mbar_init(P.mb0 + 32, 8); mbar_init(P.mb0 + 40, 8);
    }
    __syncthreads();
}
__device__ __forceinline__ void pipe_issue(PipeCtx& P, int c) {
    const int st = c % 3;
    const uint32_t mb = P.mb0 + 8u * st;
    mbar_expect_tx(mb, 2 * TILE_B);
    bulk_g2s(P.sbase + st * STAGE_B, P.Aimg + (((size_t)P.by * P.NC + c) << 14), TILE_B, mb);
    bulk_g2s(P.sbase + st * STAGE_B + TILE_B, P.Bimg + (((size_t)P.bx * P.NC + c) << 14), TILE_B, mb);
}

// ───────────────────────── fp32-acc GEMM core ────────────────────────
__device__ __forceinline__ void gemm_core_f32(
    uint32_t sbase, const char* Aimg, const char* Bimg,
    int by, int bx, int NC,
    float (&acc)[2][8][4], int tid, int wid, int lane)
{
    PipeCtx P{sbase, sbase + SMEM_MBAR, Aimg, Bimg, by, bx, NC};
    pipe_init(P, tid);
    if (tid == 0) { pipe_issue(P, 0); pipe_issue(P, 1); }

    const int wm = (wid & 3) * 32, wn = (wid >> 2) * 64;
    const int aR  = wm + (lane & 15);
    const int aK0 = (lane >> 4) * 16;
    const int bR  = wn + (lane & 7) + ((lane >> 4) << 3);
    const int bK0 = ((lane >> 3) & 1) * 16;

    for (int c = 0; c < NC; c++) {
        const int st = c % 3;
        if (tid == 0 && c + 2 < NC) {
            if (c >= 1) mbar_wait(P.mb0 + 24u + 8u * ((c - 1) % 3), ((c - 1) / 3) & 1);
            pipe_issue(P, c + 2);
        }
        mbar_wait(P.mb0 + 8u * st, (c / 3) & 1);

        const uint32_t sA = sbase + st * STAGE_B, sB = sA + TILE_B;
#pragma unroll
        for (int ks = 0; ks < 4; ks++) {
            uint32_t a[2][4], b[4][4];
#pragma unroll
            for (int i = 0; i < 2; i++) {
                const int r = aR + i * 16;
                ldmatrix4(a[i], sA + r * 128 + ((ks * 32 + aK0) ^ ((r & 7) << 4)));
            }
#pragma unroll
            for (int j = 0; j < 4; j++) {
                const int r = bR + j * 16;
                ldmatrix4(b[j], sB + r * 128 + ((ks * 32 + bK0) ^ ((r & 7) << 4)));
            }
#pragma unroll
            for (int i = 0; i < 2; i++)
#pragma unroll
                for (int j = 0; j < 4; j++) {
                    mma16816f(acc[i][2 * j],     a[i], &b[j][0]);
                    mma16816f(acc[i][2 * j + 1], a[i], &b[j][2]);
                }
        }
        if (lane == 0) mbar_arrive(P.mb0 + 24u + 8u * st);
    }
}

// ───────────────────────── fp16-acc GEMM core ────────────────────────
// acc[i][j][0] = half2 (row m+16i,  cols n, n+1); acc[i][j][1] = row m+16i+8.
__device__ __forceinline__ void gemm_core_f16(
    uint32_t sbase, const char* Aimg, const char* Bimg,
    int by, int bx, int NC,
    uint32_t (&acc)[2][8][2], int tid, int wid, int lane)
{
    PipeCtx P{sbase, sbase + SMEM_MBAR, Aimg, Bimg, by, bx, NC};
    pipe_init(P, tid);
    if (tid == 0) { pipe_issue(P, 0); pipe_issue(P, 1); }

    const int wm = (wid & 3) * 32, wn = (wid >> 2) * 64;
    const int aR  = wm + (lane & 15);
    const int aK0 = (lane >> 4) * 16;
    const int bR  = wn + (lane & 7) + ((lane >> 4) << 3);
    const int bK0 = ((lane >> 3) & 1) * 16;

    for (int c = 0; c < NC; c++) {
        const int st = c % 3;
        if (tid == 0 && c + 2 < NC) {
            if (c >= 1) mbar_wait(P.mb0 + 24u + 8u * ((c - 1) % 3), ((c - 1) / 3) & 1);
            pipe_issue(P, c + 2);
        }
        mbar_wait(P.mb0 + 8u * st, (c / 3) & 1);

        const uint32_t sA = sbase + st * STAGE_B, sB = sA + TILE_B;
#pragma unroll
        for (int ks = 0; ks < 4; ks++) {
            uint32_t a[2][4], b[4][4];
#pragma unroll
            for (int i = 0; i < 2; i++) {
                const int r = aR + i * 16;
                ldmatrix4(a[i], sA + r * 128 + ((ks * 32 + aK0) ^ ((r & 7) << 4)));
            }
#pragma unroll
            for (int j = 0; j < 4; j++) {
                const int r = bR + j * 16;
                ldmatrix4(b[j], sB + r * 128 + ((ks * 32 + bK0) ^ ((r & 7) << 4)));
            }
#pragma unroll
            for (int i = 0; i < 2; i++)
#pragma unroll
                for (int j = 0; j < 4; j++) {
                    mma16816h(acc[i][2 * j],     a[i], &b[j][0]);
                    mma16816h(acc[i][2 * j + 1], a[i], &b[j][2]);
                }
        }
        if (lane == 0) mbar_arrive(P.mb0 + 24u + 8u * st);
    }
}

// ───────────────────────── Q/K projection (fp16 acc) ─────────────────
// grid (512, 2): z=0 Q, z=1 K.
__global__ __launch_bounds__(NTH, 2) void qk_kernel(
    const float* __restrict__ bq, const float* __restrict__ bk)
{
    extern __shared__ char smem[];
    const uint32_t sbase = s2u(smem);
    const int tid = threadIdx.x, wid = tid >> 5, lane = tid & 31;
    const int z = blockIdx.y, idx = blockIdx.x;
    const int by = idx >> 3, bx = idx & 7;

    uint32_t acc[2][8][2];
#pragma unroll
    for (int i = 0; i < 2; i++)
#pragma unroll
        for (int j = 0; j < 8; j++) { acc[i][j][0] = 0u; acc[i][j][1] = 0u; }

    gemm_core_f16(sbase, (const char*)g_x, (const char*)(g_W + (size_t)z * E * D),
                  by, bx, 16, acc, tid, wid, lane);

    const int wm = (wid & 3) * 32, wn = (wid >> 2) * 64;
    const int row0 = by * 128, col0 = bx * 128;
    const float* bias = z ? bk : bq;
    __half* oH = z ? g_k : g_q;
#pragma unroll
    for (int i = 0; i < 2; i++) {
        const int m = row0 + wm + i * 16 + (lane >> 2);
#pragma unroll
        for (int j = 0; j < 8; j++) {
            const int n = col0 + wn + j * 8 + 2 * (lane & 3);
            float2 bb = *reinterpret_cast<const float2*>(bias + n);
            float2 f0 = __half22float2(*reinterpret_cast<__half2*>(&acc[i][j][0]));
            float2 f1 = __half22float2(*reinterpret_cast<__half2*>(&acc[i][j][1]));
            *reinterpret_cast<__half2*>(img_addr(oH, m, n, 16)) =
                __floats2half2_rn(f0.x + bb.x, f0.y + bb.y);
            *reinterpret_cast<__half2*>(img_addr(oH, m + 8, n, 16)) =
                __floats2half2_rn(f1.x + bb.x, f1.y + bb.y);
        }
    }
}

// ───────────────────────── V projection (fp32 acc) ───────────────────
// grid (512): rows=d (A=Wv), n=token; transposed out to g_v[b][d][s].
__global__ __launch_bounds__(NTH, 2) void v_kernel(const float* __restrict__ bv)
{
    extern __shared__ char smem[];
    const uint32_t sbase = s2u(smem);
    const int tid = threadIdx.x, wid = tid >> 5, lane = tid & 31;
    const int idx = blockIdx.x;
    const int by = idx & 7, bx = idx >> 3;

    float acc[2][8][4];
#pragma unroll
    for (int i = 0; i < 2; i++)
#pragma unroll
        for (int j = 0; j < 8; j++)
#pragma unroll
            for (int t = 0; t < 4; t++) acc[i][j][t] = 0.0f;

    gemm_core_f32(sbase, (const char*)(g_W + (size_t)2 * E * D), (const char*)g_x,
                  by, bx, 16, acc, tid, wid, lane);

    const int wm = (wid & 3) * 32, wn = (wid >> 2) * 64;
    const int row0 = by * 128, col0 = bx * 128;
#pragma unroll
    for (int i = 0; i < 2; i++) {
        const int m = row0 + wm + i * 16 + (lane >> 2);   // d index
        const float bm0 = bv[m], bm1 = bv[m + 8];
#pragma unroll
        for (int j = 0; j < 8; j++) {
            const int n = col0 + wn + j * 8 + 2 * (lane & 3);  // global token
            const int b = n >> 11, sI = n & 2047;
            __half* base = g_v + (size_t)b * D * S;
            *reinterpret_cast<__half2*>(img_addr(base, m, sI, 32)) =
                __floats2half2_rn(acc[i][j][0] + bm0, acc[i][j][1] + bm0);
            *reinterpret_cast<__half2*>(img_addr(base, m + 8, sI, 32)) =
                __floats2half2_rn(acc[i][j][2] + bm1, acc[i][j][3] + bm1);
        }
    }
}

// ───────────────────────── scores kernel (fp16 acc) ──────────────────
// p' = mask ? exp(q·k/1024) : 0  (fp16, unnormalized) + per-row partial sums.
__global__ __launch_bounds__(NTH, 2) void scores_kernel(const int* __restrict__ mask)
{
    extern __shared__ char smem[];
    const uint32_t sbase = s2u(smem);
    const int tid = threadIdx.x, wid = tid >> 5, lane = tid & 31;
    const size_t z = blockIdx.z;
    const int by = blockIdx.y, bx = blockIdx.x;

    uint32_t acc[2][8][2];
#pragma unroll
    for (int i = 0; i < 2; i++)
#pragma unroll
        for (int j = 0; j < 8; j++) { acc[i][j][0] = 0u; acc[i][j][1] = 0u; }

    gemm_core_f16(sbase, (const char*)(g_q + z * (size_t)S * D),
                  (const char*)(g_k + z * (size_t)S * D), by, bx, 16, acc, tid, wid, lane);

    const int wm = (wid & 3) * 32, wn = (wid >> 2) * 64;
    const int row0 = by * 128, col0 = bx * 128;
    const float sc = 1.0f / 1024.0f;
    const int* mbase = mask + z * (size_t)S * S;
    __half* pbase = g_p + z * (size_t)S * S;
    float* rs = g_rs + z * (size_t)S * 32;
    const int slot = bx * 2 + (wid >> 2);

#pragma unroll
    for (int i = 0; i < 2; i++) {
        const int m = row0 + wm + i * 16 + (lane >> 2);
        float s0 = 0.0f, s1 = 0.0f;
#pragma unroll
        for (int j = 0; j < 8; j++) {
            const int n = col0 + wn + j * 8 + 2 * (lane & 3);
            float2 f0 = __half22float2(*reinterpret_cast<__half2*>(&acc[i][j][0]));
            float2 f1 = __half22float2(*reinterpret_cast<__half2*>(&acc[i][j][1]));
            int2 mk = *reinterpret_cast<const int2*>(mbase + (size_t)m * S + n);
            float p00 = mk.x ? __expf(f0.x * sc) : 0.0f;
            float p01 = mk.y ? __expf(f0.y * sc) : 0.0f;
            mk = *reinterpret_cast<const int2*>(mbase + (size_t)(m + 8) * S + n);
            float p10 = mk.x ? __expf(f1.x * sc) : 0.0f;
            float p11 = mk.y ? __expf(f1.y * sc) : 0.0f;
            *reinterpret_cast<__half2*>(img_addr(pbase, m, n, 32))     = __floats2half2_rn(p00, p01);
            *reinterpret_cast<__half2*>(img_addr(pbase, m + 8, n, 32)) = __floats2half2_rn(p10, p11);
            s0 += p00 + p01;
            s1 += p10 + p11;
        }
        s0 += __shfl_xor_sync(0xFFFFFFFF, s0, 1);
        s0 += __shfl_xor_sync(0xFFFFFFFF, s0, 2);
        s1 += __shfl_xor_sync(0xFFFFFFFF, s1, 1);
        s1 += __shfl_xor_sync(0xFFFFFFFF, s1, 2);
        if ((lane & 3) == 0) {
            rs[(size_t)m * 32 + slot]       = s0;
            rs[(size_t)(m + 8) * 32 + slot] = s1;
        }
    }
}

// ───────────────────────── PV kernel (fp32 acc) ──────────────────────
// out = (P' @ V) / rowsum.
__global__ __launch_bounds__(NTH, 2) void pv_kernel(float* __restrict__ outF)
{
    extern __shared__ char smem[];
    __shared__ float s_inv[128];
    const uint32_t sbase = s2u(smem);
    const int tid = threadIdx.x, wid = tid >> 5, lane = tid & 31;
    const size_t z = blockIdx.z;
    const int by = blockIdx.y, bx = blockIdx.x;

    if (tid < 128) {
        const float* p = g_rs + (z * (size_t)S + by * 128 + tid) * 32;
        float s = 0.0f;
#pragma unroll
        for (int k = 0; k < 32; k++) s += p[k];
        s_inv[tid] = 1.0f / s;
    }
    // pipe_init's __syncthreads orders s_inv before its reads below.

    float acc[2][8][4];
#pragma unroll
    for (int i = 0; i < 2; i++)
#pragma unroll
        for (int j = 0; j < 8; j++)
#pragma unroll
            for (int t = 0; t < 4; t++) acc[i][j][t] = 0.0f;

    gemm_core_f32(sbase, (const char*)(g_p + z * (size_t)S * S),
                  (const char*)(g_v + z * (size_t)D * S), by, bx, 32, acc, tid, wid, lane);

    const int wm = (wid & 3) * 32, wn = (wid >> 2) * 64;
    const int row0 = by * 128, col0 = bx * 128;
    float* O = outF + z * (size_t)S * D;

#pragma unroll
    for (int i = 0; i < 2; i++) {
        const int ml = wm + i * 16 + (lane >> 2);
        const int m = row0 + ml;
        const float inv0 = s_inv[ml], inv1 = s_inv[ml + 8];
#pragma unroll
        for (int j = 0; j < 8; j++) {
            const int n = col0 + wn + j * 8 + 2 * (lane & 3);
            float2 o;
            o.x = acc[i][j][0] * inv0; o.y = acc[i][j][1] * inv0;
            *reinterpret_cast<float2*>(O + (size_t)m * D + n) = o;
            o.x = acc[i][j][2] * inv1; o.y = acc[i][j][3] * inv1;
            *reinterpret_cast<float2*>(O + (size_t)(m + 8) * D + n) = o;
        }
    }
}

// ───────────────────────── conversion kernels ────────────────────────
__global__ __launch_bounds__(256) void convert_x_kernel(const float* __restrict__ x) {
    const uint32_t uid = blockIdx.x * 256 + threadIdx.x;
    const int r = uid >> 7;
    const int k = (uid & 127) * 8;
    const float4* src = reinterpret_cast<const float4*>(x + (size_t)r * E + k);
    float4 v0 = src[0], v1 = src[1];
    __half2 h[4];
    h[0] = __floats2half2_rn(v0.x, v0.y);
    h[1] = __floats2half2_rn(v0.z, v0.w);
    h[2] = __floats2half2_rn(v1.x, v1.y);
    h[3] = __floats2half2_rn(v1.z, v1.w);
    *reinterpret_cast<uint4*>(img_addr(g_x, r, k, 16)) = *reinterpret_cast<uint4*>(h);
}

__global__ __launch_bounds__(256) void convert_w_kernel(
    const float* __restrict__ Wq, const float* __restrict__ Wk, const float* __restrict__ Wv)
{
    const float* W = (blockIdx.z == 0) ? Wq : (blockIdx.z == 1) ? Wk : Wv;
    __half* o = g_W + (size_t)blockIdx.z * E * D;

    __shared__ float t[32][33];
    const int tx = threadIdx.x & 31, ty = threadIdx.x >> 5;
    const int nb = blockIdx.x * 32, eb = blockIdx.y * 32;
#pragma unroll
    for (int i = 0; i < 4; i++) {
        int e = eb + ty + i * 8;
        t[ty + i * 8][tx] = W[(size_t)e * D + nb + tx];
    }
    __syncthreads();
#pragma unroll
    for (int j = 0; j < 2; j++) {
        const int idx = j * 256 + threadIdx.x;
        const int nl = idx & 31, ep = idx >> 5;
        const int n = nb + nl, e = eb + ep * 2;
        *reinterpret_cast<__half2*>(img_addr(o, n, e, 16)) =
            __floats2half2_rn(t[ep * 2][nl], t[ep * 2 + 1][nl]);
    }
}

// ───────────────────────── host launch ───────────────────────────────
extern "C" void kernel_launch(void* const* d_in, const int* in_sizes, int n_in,
                              void* d_out, int out_size)
{
    const float* x    = (const float*)d_in[0];
    const int*   mask = (const int*)  d_in[1];
    const float* Wq   = (const float*)d_in[2];
    const float* bq   = (const float*)d_in[3];
    const float* Wk   = (const float*)d_in[4];
    const float* bk   = (const float*)d_in[5];
    const float* Wv   = (const float*)d_in[6];
    const float* bv   = (const float*)d_in[7];
    float* out = (float*)d_out;

    cudaFuncSetAttribute(qk_kernel,     cudaFuncAttributeMaxDynamicSharedMemorySize, SMEM_TOTAL);
    cudaFuncSetAttribute(v_kernel,      cudaFuncAttributeMaxDynamicSharedMemorySize, SMEM_TOTAL);
    cudaFuncSetAttribute(scores_kernel, cudaFuncAttributeMaxDynamicSharedMemorySize, SMEM_TOTAL);
    cudaFuncSetAttribute(pv_kernel,     cudaFuncAttributeMaxDynamicSharedMemorySize, SMEM_TOTAL);

    // 1) fp32 -> fp16 tiled-swizzled images
    convert_x_kernel<<<(unsigned)((size_t)Bsz * S * E / 8 / 256), 256>>>(x);
    convert_w_kernel<<<dim3(D / 32, E / 32, 3), 256>>>(Wq, Wk, Wv);

    // 2) projections: Q,K (fp16 acc), V (fp32 acc, transposed out)
    qk_kernel<<<dim3(512, 2), NTH, SMEM_TOTAL>>>(bq, bk);
    v_kernel<<<512, NTH, SMEM_TOTAL>>>(bv);

    // 3) scores + mask + exp + row partial sums (fp16 acc)
    scores_kernel<<<dim3(S / 128, S / 128, Bsz), NTH, SMEM_TOTAL>>>(mask);

    // 4) out = (P' @ V) / rowsum (fp32 acc)
    pv_kernel<<<dim3(D / 128, S / 128, Bsz), NTH, SMEM_TOTAL>>>(out);
}

// round 16
// speedup vs baseline: 1.0215x; 1.0215x over previous
#include <cuda_runtime.h>
#include <cuda_fp16.h>
#include <cstdint>
#include <math.h>

// ───────────────────────── problem constants ─────────────────────────
constexpr int Bsz = 4, S = 2048, E = 1024, D = 1024;

// Tiled-swizzled image format for all fp16 operands:
//   tile (rb, kb) = 128 rows × 64 k = 16KB contiguous at (rb*NKB + kb)*16384,
//   element (ir, ik) at byte ir*128 + ((ik*2) ^ ((ir&7)<<4)).
__device__ __half g_x[(size_t)Bsz * S * E];      // rows=token, k=e   (NKB 16)
__device__ __half g_W[(size_t)3 * E * D];        // per z: rows=n, k=e (NKB 16)
__device__ __half g_q[(size_t)Bsz * S * D];      // rows=token, k=d   (NKB 16)
__device__ __half g_k[(size_t)Bsz * S * D];      // rows=token, k=d   (NKB 16)
__device__ __half g_v[(size_t)Bsz * D * S];      // per b: rows=d, k=s (NKB 32)
__device__ __half g_p[(size_t)Bsz * S * S];      // exp'd unnormalized probs (NKB 32)
__device__ float  g_rs[(size_t)Bsz * S * 32];    // per-row partial sums (32 slots)

__device__ __forceinline__ __half* img_addr(__half* base, int r, int k, int nkb) {
    size_t tile = (size_t)((r >> 7) * nkb + (k >> 6));
    uint32_t off = (uint32_t)((r & 127) * 128) +
                   ((((uint32_t)(k & 63)) * 2) ^ (((uint32_t)r & 7) << 4));
    return (__half*)((char*)base + (tile << 14) + off);
}

// ───────────────────────── tile config ───────────────────────────────
constexpr int NTH = 256;
constexpr int TILE_B = 16384;                  // 128 x 64 halfs
constexpr int STAGE_B = 2 * TILE_B;            // A, B
constexpr int SMEM_MBAR = 3 * STAGE_B;         // 98304
constexpr int SMEM_TOTAL = SMEM_MBAR + 64;

// ───────────────────────── PTX helpers ───────────────────────────────
__device__ __forceinline__ uint32_t s2u(const void* p) {
    uint32_t a;
    asm("{ .reg .u64 t; cvta.to.shared.u64 t, %1; cvt.u32.u64 %0, t; }" : "=r"(a) : "l"(p));
    return a;
}
__device__ __forceinline__ void mbar_init(uint32_t addr, uint32_t cnt) {
    asm volatile("mbarrier.init.shared.b64 [%0], %1;" :: "r"(addr), "r"(cnt) : "memory");
}
__device__ __forceinline__ void mbar_expect_tx(uint32_t addr, uint32_t bytes) {
    asm volatile("mbarrier.arrive.expect_tx.shared::cta.b64 _, [%0], %1;"
                 :: "r"(addr), "r"(bytes) : "memory");
}
__device__ __forceinline__ void mbar_arrive(uint32_t addr) {
    asm volatile("mbarrier.arrive.shared.b64 _, [%0];" :: "r"(addr) : "memory");
}
__device__ __forceinline__ void mbar_wait(uint32_t addr, uint32_t parity) {
    asm volatile(
        "{\n\t.reg .pred P;\n\t"
        "WL_%=:\n\t"
        "mbarrier.try_wait.parity.acquire.cta.shared::cta.b64 P, [%0], %1, 0x989680;\n\t"
        "@!P bra WL_%=;\n\t}"
        :: "r"(addr), "r"(parity) : "memory");
}
__device__ __forceinline__ void bulk_g2s(uint32_t sdst, const void* gsrc, uint32_t bytes,
                                         uint32_t mbar) {
    asm volatile(
        "cp.async.bulk.shared::cluster.global.mbarrier::complete_tx::bytes "
        "[%0], [%1], %2, [%3];"
        :: "r"(sdst), "l"(gsrc), "r"(bytes), "r"(mbar) : "memory");
}
__device__ __forceinline__ void ldmatrix4(uint32_t* r, uint32_t addr) {
    asm volatile("ldmatrix.sync.aligned.m8n8.x4.shared.b16 {%0,%1,%2,%3}, [%4];"
                 : "=r"(r[0]), "=r"(r[1]), "=r"(r[2]), "=r"(r[3]) : "r"(addr));
}
__device__ __forceinline__ void mma16816f(float* c, const uint32_t* a, const uint32_t* b) {
    asm volatile(
        "mma.sync.aligned.m16n8k16.row.col.f32.f16.f16.f32 "
        "{%0,%1,%2,%3}, {%4,%5,%6,%7}, {%8,%9}, {%0,%1,%2,%3};"
        : "+f"(c[0]), "+f"(c[1]), "+f"(c[2]), "+f"(c[3])
        : "r"(a[0]), "r"(a[1]), "r"(a[2]), "r"(a[3]), "r"(b[0]), "r"(b[1]));
}
__device__ __forceinline__ void mma16816h(uint32_t* c, const uint32_t* a, const uint32_t* b) {
    asm volatile(
        "mma.sync.aligned.m16n8k16.row.col.f16.f16.f16.f16 "
        "{%0,%1}, {%2,%3,%4,%5}, {%6,%7}, {%0,%1};"
        : "+r"(c[0]), "+r"(c[1])
        : "r"(a[0]), "r"(a[1]), "r"(a[2]), "r"(a[3]), "r"(b[0]), "r"(b[1]));
}

// ───────────────────────── pipeline machinery (shared) ───────────────
struct PipeCtx {
    uint32_t sbase, mb0;
    const char *Aimg, *Bimg;
    int by, bx, NC;
};

__device__ __forceinline__ void pipe_init(PipeCtx& P, int tid) {
    if (tid == 0) {
        mbar_init(P.mb0, 1);      mbar_init(P.mb0 + 8, 1);  mbar_init(P.mb0 + 16, 1);
        mbar_init(P.mb0 + 24, 8); mbar_init(P.mb0 + 32, 8); mbar_init(P.mb0 + 40, 8);
    }
    __syncthreads();
}
__device__ __forceinline__ void pipe_issue(PipeCtx& P, int c) {
    const int st = c % 3;
    const uint32_t mb = P.mb0 + 8u * st;
    mbar_expect_tx(mb, 2 * TILE_B);
    bulk_g2s(P.sbase + st * STAGE_B, P.Aimg + (((size_t)P.by * P.NC + c) << 14), TILE_B, mb);
    bulk_g2s(P.sbase + st * STAGE_B + TILE_B, P.Bimg + (((size_t)P.bx * P.NC + c) << 14), TILE_B, mb);
}

// ───────────────────────── fp32-acc GEMM core ────────────────────────
__device__ __forceinline__ void gemm_core_f32(
    uint32_t sbase, const char* Aimg, const char* Bimg,
    int by, int bx, int NC,
    float (&acc)[2][8][4], int tid, int wid, int lane)
{
    PipeCtx P{sbase, sbase + SMEM_MBAR, Aimg, Bimg, by, bx, NC};
    pipe_init(P, tid);
    if (tid == 0) { pipe_issue(P, 0); pipe_issue(P, 1); }

    const int wm = (wid & 3) * 32, wn = (wid >> 2) * 64;
    const int aR  = wm + (lane & 15);
    const int aK0 = (lane >> 4) * 16;
    const int bR  = wn + (lane & 7) + ((lane >> 4) << 3);
    const int bK0 = ((lane >> 3) & 1) * 16;

    for (int c = 0; c < NC; c++) {
        const int st = c % 3;
        if (tid == 0 && c + 2 < NC) {
            if (c >= 1) mbar_wait(P.mb0 + 24u + 8u * ((c - 1) % 3), ((c - 1) / 3) & 1);
            pipe_issue(P, c + 2);
        }
        mbar_wait(P.mb0 + 8u * st, (c / 3) & 1);

        const uint32_t sA = sbase + st * STAGE_B, sB = sA + TILE_B;
#pragma unroll
        for (int ks = 0; ks < 4; ks++) {
            uint32_t a[2][4], b[4][4];
#pragma unroll
            for (int i = 0; i < 2; i++) {
                const int r = aR + i * 16;
                ldmatrix4(a[i], sA + r * 128 + ((ks * 32 + aK0) ^ ((r & 7) << 4)));
            }
#pragma unroll
            for (int j = 0; j < 4; j++) {
                const int r = bR + j * 16;
                ldmatrix4(b[j], sB + r * 128 + ((ks * 32 + bK0) ^ ((r & 7) << 4)));
            }
#pragma unroll
            for (int i = 0; i < 2; i++)
#pragma unroll
                for (int j = 0; j < 4; j++) {
                    mma16816f(acc[i][2 * j],     a[i], &b[j][0]);
                    mma16816f(acc[i][2 * j + 1], a[i], &b[j][2]);
                }
        }
        if (lane == 0) mbar_arrive(P.mb0 + 24u + 8u * st);
    }
}

// ───────────────────────── fp16-acc GEMM core ────────────────────────
__device__ __forceinline__ void gemm_core_f16(
    uint32_t sbase, const char* Aimg, const char* Bimg,
    int by, int bx, int NC,
    uint32_t (&acc)[2][8][2], int tid, int wid, int lane)
{
    PipeCtx P{sbase, sbase + SMEM_MBAR, Aimg, Bimg, by, bx, NC};
    pipe_init(P, tid);
    if (tid == 0) { pipe_issue(P, 0); pipe_issue(P, 1); }

    const int wm = (wid & 3) * 32, wn = (wid >> 2) * 64;
    const int aR  = wm + (lane & 15);
    const int aK0 = (lane >> 4) * 16;
    const int bR  = wn + (lane & 7) + ((lane >> 4) << 3);
    const int bK0 = ((lane >> 3) & 1) * 16;

    for (int c = 0; c < NC; c++) {
        const int st = c % 3;
        if (tid == 0 && c + 2 < NC) {
            if (c >= 1) mbar_wait(P.mb0 + 24u + 8u * ((c - 1) % 3), ((c - 1) / 3) & 1);
            pipe_issue(P, c + 2);
        }
        mbar_wait(P.mb0 + 8u * st, (c / 3) & 1);

        const uint32_t sA = sbase + st * STAGE_B, sB = sA + TILE_B;
#pragma unroll
        for (int ks = 0; ks < 4; ks++) {
            uint32_t a[2][4], b[4][4];
#pragma unroll
            for (int i = 0; i < 2; i++) {
                const int r = aR + i * 16;
                ldmatrix4(a[i], sA + r * 128 + ((ks * 32 + aK0) ^ ((r & 7) << 4)));
            }
#pragma unroll
            for (int j = 0; j < 4; j++) {
                const int r = bR + j * 16;
                ldmatrix4(b[j], sB + r * 128 + ((ks * 32 + bK0) ^ ((r & 7) << 4)));
            }
#pragma unroll
            for (int i = 0; i < 2; i++)
#pragma unroll
                for (int j = 0; j < 4; j++) {
                    mma16816h(acc[i][2 * j],     a[i], &b[j][0]);
                    mma16816h(acc[i][2 * j + 1], a[i], &b[j][2]);
                }
        }
        if (lane == 0) mbar_arrive(P.mb0 + 24u + 8u * st);
    }
}

// ───────────────────────── merged QKV kernel ─────────────────────────
// Flat grid 1536: blocks 0..511  -> V projection (fp32 acc, longer CTAs, first)
//                 blocks 512..1535 -> Q (z=0) / K (z=1) projection (fp16 acc)
__global__ __launch_bounds__(NTH, 2) void qkv_kernel(
    const float* __restrict__ bq, const float* __restrict__ bk, const float* __restrict__ bv)
{
    extern __shared__ char smem[];
    const uint32_t sbase = s2u(smem);
    const int tid = threadIdx.x, wid = tid >> 5, lane = tid & 31;
    const int bid = blockIdx.x;
    const int wm = (wid & 3) * 32, wn = (wid >> 2) * 64;

    if (bid < 512) {
        // ── V path (fp32 acc): rows=d (A=Wv), n=token; out g_v[b][d][s] ──
        const int by = bid & 7, bx = bid >> 3;

        float acc[2][8][4];
#pragma unroll
        for (int i = 0; i < 2; i++)
#pragma unroll
            for (int j = 0; j < 8; j++)
#pragma unroll
                for (int t = 0; t < 4; t++) acc[i][j][t] = 0.0f;

        gemm_core_f32(sbase, (const char*)(g_W + (size_t)2 * E * D), (const char*)g_x,
                      by, bx, 16, acc, tid, wid, lane);

        const int row0 = by * 128, col0 = bx * 128;
#pragma unroll
        for (int i = 0; i < 2; i++) {
            const int m = row0 + wm + i * 16 + (lane >> 2);   // d index
            const float bm0 = bv[m], bm1 = bv[m + 8];
#pragma unroll
            for (int j = 0; j < 8; j++) {
                const int n = col0 + wn + j * 8 + 2 * (lane & 3);  // global token
                const int b = n >> 11, sI = n & 2047;
                __half* base = g_v + (size_t)b * D * S;
                *reinterpret_cast<__half2*>(img_addr(base, m, sI, 32)) =
                    __floats2half2_rn(acc[i][j][0] + bm0, acc[i][j][1] + bm0);
                *reinterpret_cast<__half2*>(img_addr(base, m + 8, sI, 32)) =
                    __floats2half2_rn(acc[i][j][2] + bm1, acc[i][j][3] + bm1);
            }
        }
    } else {
        // ── Q/K path (fp16 acc) ──
        const int t = bid - 512;
        const int z = t >> 9, idx = t & 511;
        const int by = idx >> 3, bx = idx & 7;

        uint32_t acc[2][8][2];
#pragma unroll
        for (int i = 0; i < 2; i++)
#pragma unroll
            for (int j = 0; j < 8; j++) { acc[i][j][0] = 0u; acc[i][j][1] = 0u; }

        gemm_core_f16(sbase, (const char*)g_x, (const char*)(g_W + (size_t)z * E * D),
                      by, bx, 16, acc, tid, wid, lane);

        const int row0 = by * 128, col0 = bx * 128;
        const float* bias = z ? bk : bq;
        __half* oH = z ? g_k : g_q;
#pragma unroll
        for (int i = 0; i < 2; i++) {
            const int m = row0 + wm + i * 16 + (lane >> 2);
#pragma unroll
            for (int j = 0; j < 8; j++) {
                const int n = col0 + wn + j * 8 + 2 * (lane & 3);
                float2 bb = *reinterpret_cast<const float2*>(bias + n);
                float2 f0 = __half22float2(*reinterpret_cast<__half2*>(&acc[i][j][0]));
                float2 f1 = __half22float2(*reinterpret_cast<__half2*>(&acc[i][j][1]));
                *reinterpret_cast<__half2*>(img_addr(oH, m, n, 16)) =
                    __floats2half2_rn(f0.x + bb.x, f0.y + bb.y);
                *reinterpret_cast<__half2*>(img_addr(oH, m + 8, n, 16)) =
                    __floats2half2_rn(f1.x + bb.x, f1.y + bb.y);
            }
        }
    }
}

// ───────────────────────── scores kernel (fp16 acc) ──────────────────
// p' = mask ? exp(q·k/1024) : 0  (fp16, unnormalized) + per-row partial sums.
__global__ __launch_bounds__(NTH, 2) void scores_kernel(const int* __restrict__ mask)
{
    extern __shared__ char smem[];
    const uint32_t sbase = s2u(smem);
    const int tid = threadIdx.x, wid = tid >> 5, lane = tid & 31;
    const size_t z = blockIdx.z;
    const int by = blockIdx.y, bx = blockIdx.x;

    uint32_t acc[2][8][2];
#pragma unroll
    for (int i = 0; i < 2; i++)
#pragma unroll
        for (int j = 0; j < 8; j++) { acc[i][j][0] = 0u; acc[i][j][1] = 0u; }

    gemm_core_f16(sbase, (const char*)(g_q + z * (size_t)S * D),
                  (const char*)(g_k + z * (size_t)S * D), by, bx, 16, acc, tid, wid, lane);

    const int wm = (wid & 3) * 32, wn = (wid >> 2) * 64;
    const int row0 = by * 128, col0 = bx * 128;
    const float sc = 1.0f / 1024.0f;
    const int* mbase = mask + z * (size_t)S * S;
    __half* pbase = g_p + z * (size_t)S * S;
    float* rs = g_rs + z * (size_t)S * 32;
    const int slot = bx * 2 + (wid >> 2);

#pragma unroll
    for (int i = 0; i < 2; i++) {
        const int m = row0 + wm + i * 16 + (lane >> 2);
        float s0 = 0.0f, s1 = 0.0f;
#pragma unroll
        for (int j = 0; j < 8; j++) {
            const int n = col0 + wn + j * 8 + 2 * (lane & 3);
            float2 f0 = __half22float2(*reinterpret_cast<__half2*>(&acc[i][j][0]));
            float2 f1 = __half22float2(*reinterpret_cast<__half2*>(&acc[i][j][1]));
            int2 mk = *reinterpret_cast<const int2*>(mbase + (size_t)m * S + n);
            float p00 = mk.x ? __expf(f0.x * sc) : 0.0f;
            float p01 = mk.y ? __expf(f0.y * sc) : 0.0f;
            mk = *reinterpret_cast<const int2*>(mbase + (size_t)(m + 8) * S + n);
            float p10 = mk.x ? __expf(f1.x * sc) : 0.0f;
            float p11 = mk.y ? __expf(f1.y * sc) : 0.0f;
            *reinterpret_cast<__half2*>(img_addr(pbase, m, n, 32))     = __floats2half2_rn(p00, p01);
            *reinterpret_cast<__half2*>(img_addr(pbase, m + 8, n, 32)) = __floats2half2_rn(p10, p11);
            s0 += p00 + p01;
            s1 += p10 + p11;
        }
        s0 += __shfl_xor_sync(0xFFFFFFFF, s0, 1);
        s0 += __shfl_xor_sync(0xFFFFFFFF, s0, 2);
        s1 += __shfl_xor_sync(0xFFFFFFFF, s1, 1);
        s1 += __shfl_xor_sync(0xFFFFFFFF, s1, 2);
        if ((lane & 3) == 0) {
            rs[(size_t)m * 32 + slot]       = s0;
            rs[(size_t)(m + 8) * 32 + slot] = s1;
        }
    }
}

// ───────────────────────── PV kernel (fp32 acc) ──────────────────────
// out = (P' @ V) / rowsum.
__global__ __launch_bounds__(NTH, 2) void pv_kernel(float* __restrict__ outF)
{
    extern __shared__ char smem[];
    __shared__ float s_inv[128];
    const uint32_t sbase = s2u(smem);
    const int tid = threadIdx.x, wid = tid >> 5, lane = tid & 31;
    const size_t z = blockIdx.z;
    const int by = blockIdx.y, bx = blockIdx.x;

    if (tid < 128) {
        const float* p = g_rs + (z * (size_t)S + by * 128 + tid) * 32;
        float s = 0.0f;
#pragma unroll
        for (int k = 0; k < 32; k++) s += p[k];
        s_inv[tid] = 1.0f / s;
    }
    // pipe_init's __syncthreads orders s_inv before its reads below.

    float acc[2][8][4];
#pragma unroll
    for (int i = 0; i < 2; i++)
#pragma unroll
        for (int j = 0; j < 8; j++)
#pragma unroll
            for (int t = 0; t < 4; t++) acc[i][j][t] = 0.0f;

    gemm_core_f32(sbase, (const char*)(g_p + z * (size_t)S * S),
                  (const char*)(g_v + z * (size_t)D * S), by, bx, 32, acc, tid, wid, lane);

    const int wm = (wid & 3) * 32, wn = (wid >> 2) * 64;
    const int row0 = by * 128, col0 = bx * 128;
    float* O = outF + z * (size_t)S * D;

#pragma unroll
    for (int i = 0; i < 2; i++) {
        const int ml = wm + i * 16 + (lane >> 2);
        const int m = row0 + ml;
        const float inv0 = s_inv[ml], inv1 = s_inv[ml + 8];
#pragma unroll
        for (int j = 0; j < 8; j++) {
            const int n = col0 + wn + j * 8 + 2 * (lane & 3);
            float2 o;
            o.x = acc[i][j][0] * inv0; o.y = acc[i][j][1] * inv0;
            *reinterpret_cast<float2*>(O + (size_t)m * D + n) = o;
            o.x = acc[i][j][2] * inv1; o.y = acc[i][j][3] * inv1;
            *reinterpret_cast<float2*>(O + (size_t)(m + 8) * D + n) = o;
        }
    }
}

// ───────────────────────── merged conversion kernel ──────────────────
// Flat grid 7168: blocks 0..4095 -> x, blocks 4096..7167 -> W (3 x 32 x 32).
__global__ __launch_bounds__(256) void convert_kernel(
    const float* __restrict__ x,
    const float* __restrict__ Wq, const float* __restrict__ Wk, const float* __restrict__ Wv)
{
    const int bid = blockIdx.x;
    if (bid < 4096) {
        const uint32_t uid = bid * 256 + threadIdx.x;
        const int r = uid >> 7;
        const int k = (uid & 127) * 8;
        const float4* src = reinterpret_cast<const float4*>(x + (size_t)r * E + k);
        float4 v0 = src[0], v1 = src[1];
        __half2 h[4];
        h[0] = __floats2half2_rn(v0.x, v0.y);
        h[1] = __floats2half2_rn(v0.z, v0.w);
        h[2] = __floats2half2_rn(v1.x, v1.y);
        h[3] = __floats2half2_rn(v1.z, v1.w);
        *reinterpret_cast<uint4*>(img_addr(g_x, r, k, 16)) = *reinterpret_cast<uint4*>(h);
    } else {
        const int t = bid - 4096;
        const int z = t >> 10, bxx = t & 31, byy = (t >> 5) & 31;
        const float* W = (z == 0) ? Wq : (z == 1) ? Wk : Wv;
        __half* o = g_W + (size_t)z * E * D;

        __shared__ float tr[32][33];
        const int tx = threadIdx.x & 31, ty = threadIdx.x >> 5;
        const int nb = bxx * 32, eb = byy * 32;
#pragma unroll
        for (int i = 0; i < 4; i++) {
            int e = eb + ty + i * 8;
            tr[ty + i * 8][tx] = W[(size_t)e * D + nb + tx];
        }
        __syncthreads();
#pragma unroll
        for (int j = 0; j < 2; j++) {
            const int idx = j * 256 + threadIdx.x;
            const int nl = idx & 31, ep = idx >> 5;
            const int n = nb + nl, e = eb + ep * 2;
            *reinterpret_cast<__half2*>(img_addr(o, n, e, 16)) =
                __floats2half2_rn(tr[ep * 2][nl], tr[ep * 2 + 1][nl]);
        }
    }
}

// ───────────────────────── host launch ───────────────────────────────
extern "C" void kernel_launch(void* const* d_in, const int* in_sizes, int n_in,
                              void* d_out, int out_size)
{
    const float* x    = (const float*)d_in[0];
    const int*   mask = (const int*)  d_in[1];
    const float* Wq   = (const float*)d_in[2];
    const float* bq   = (const float*)d_in[3];
    const float* Wk   = (const float*)d_in[4];
    const float* bk   = (const float*)d_in[5];
    const float* Wv   = (const float*)d_in[6];
    const float* bv   = (const float*)d_in[7];
    float* out = (float*)d_out;

    cudaFuncSetAttribute(qkv_kernel,    cudaFuncAttributeMaxDynamicSharedMemorySize, SMEM_TOTAL);
    cudaFuncSetAttribute(scores_kernel, cudaFuncAttributeMaxDynamicSharedMemorySize, SMEM_TOTAL);
    cudaFuncSetAttribute(pv_kernel,     cudaFuncAttributeMaxDynamicSharedMemorySize, SMEM_TOTAL);

    // 1) fp32 -> fp16 tiled-swizzled images (x + W, one launch)
    convert_kernel<<<7168, 256>>>(x, Wq, Wk, Wv);

    // 2) projections: V (fp32 acc, long CTAs first) + Q/K (fp16 acc), one launch
    qkv_kernel<<<1536, NTH, SMEM_TOTAL>>>(bq, bk, bv);

    // 3) scores + mask + exp + row partial sums (fp16 acc)
    scores_kernel<<<dim3(S / 128, S / 128, Bsz), NTH, SMEM_TOTAL>>>(mask);

    // 4) out = (P' @ V) / rowsum (fp32 acc)
    pv_kernel<<<dim3(D / 128, S / 128, Bsz), NTH, SMEM_TOTAL>>>(out);
}